// round 2
// baseline (speedup 1.0000x reference)
#include <cuda_runtime.h>
#include <math.h>

#define TT 1536
#define CC 1536
#define HH 8
#define HK 64
#define HV 192
#define FF 192
#define LL (2*TT-1)      // 3071
#define QKC (HH*HK)      // 512

// ---------------- scratch (device globals; allocation-free) ----------------
__device__ float g_xn[TT*CC];
__device__ float g_q [TT*QKC];
__device__ float g_k [TT*QKC];
__device__ float g_v [TT*CC];
__device__ float g_pos[LL*FF];
__device__ float g_rk [LL*QKC];
__device__ float g_logits[(size_t)HH*TT*TT];   // 75.5 MB, reused as attn
__device__ float g_o [TT*CC];
__device__ float g_y [TT*CC];
__device__ float g_yn[TT*CC];
__device__ float g_h1[TT*2*CC];

// ---------------- LayerNorm ----------------
__global__ void ln_kernel(const float* __restrict__ x, const float* __restrict__ g,
                          const float* __restrict__ b, float* __restrict__ out) {
    int row = blockIdx.x;
    const float* xr = x + (size_t)row * CC;
    float s = 0.f, sq = 0.f;
    for (int c = threadIdx.x; c < CC; c += blockDim.x) { float v = xr[c]; s += v; sq += v*v; }
    __shared__ float rs[256], rq[256];
    rs[threadIdx.x] = s; rq[threadIdx.x] = sq; __syncthreads();
    for (int st = 128; st > 0; st >>= 1) {
        if (threadIdx.x < st) { rs[threadIdx.x] += rs[threadIdx.x+st]; rq[threadIdx.x] += rq[threadIdx.x+st]; }
        __syncthreads();
    }
    float mean = rs[0] / CC;
    float var  = rq[0] / CC - mean*mean;
    float rstd = rsqrtf(var + 1e-3f);
    for (int c = threadIdx.x; c < CC; c += blockDim.x)
        out[(size_t)row*CC + c] = (xr[c] - mean) * rstd * g[c] + b[c];
}

// ---------------- generic batched SGEMM: C = alpha*A@B (+bias)(relu)(+res) ----------------
__global__ __launch_bounds__(256)
void gemm_kernel(int M, int N, int K,
                 const float* __restrict__ A, int lda, long long sA,
                 const float* __restrict__ B, int ldb, long long sB,
                 float* __restrict__ Cp, int ldc, long long sC,
                 const float* __restrict__ bias,
                 const float* __restrict__ Rp, int ldr, long long sR,
                 float alpha, int relu)
{
    int bz = blockIdx.z;
    A  += (long long)bz * sA;
    B  += (long long)bz * sB;
    Cp += (long long)bz * sC;
    const float* Rb = Rp ? Rp + (long long)bz * sR : nullptr;

    int bm = blockIdx.y * 128, bn = blockIdx.x * 128;
    __shared__ float As[8][128];
    __shared__ float Bs[8][128];
    int tid = threadIdx.x;
    float acc[8][8];
#pragma unroll
    for (int i = 0; i < 8; i++)
#pragma unroll
        for (int j = 0; j < 8; j++) acc[i][j] = 0.f;

    int arow = tid >> 1, akk = (tid & 1) * 4;
    int bkk  = tid >> 5, bnn = (tid & 31) * 4;
    int r0 = (tid >> 4) * 8, c0 = (tid & 15) * 8;

    for (int k0 = 0; k0 < K; k0 += 8) {
        float4 av = make_float4(0,0,0,0);
        if (bm + arow < M)
            av = *(const float4*)&A[(long long)(bm + arow) * lda + k0 + akk];
        As[akk+0][arow] = av.x; As[akk+1][arow] = av.y;
        As[akk+2][arow] = av.z; As[akk+3][arow] = av.w;

        float4 bv = make_float4(0,0,0,0);
        if (bn + bnn < N)
            bv = *(const float4*)&B[(long long)(k0 + bkk) * ldb + bn + bnn];
        *(float4*)&Bs[bkk][bnn] = bv;
        __syncthreads();

#pragma unroll 8
        for (int kk = 0; kk < 8; kk++) {
            float a[8], b[8];
            *(float4*)&a[0] = *(float4*)&As[kk][r0];
            *(float4*)&a[4] = *(float4*)&As[kk][r0+4];
            *(float4*)&b[0] = *(float4*)&Bs[kk][c0];
            *(float4*)&b[4] = *(float4*)&Bs[kk][c0+4];
#pragma unroll
            for (int i = 0; i < 8; i++)
#pragma unroll
                for (int j = 0; j < 8; j++)
                    acc[i][j] += a[i] * b[j];
        }
        __syncthreads();
    }

    const bool has_bias = (bias != nullptr);
    const bool has_res  = (Rb != nullptr);
#pragma unroll
    for (int i = 0; i < 8; i++) {
        int m = bm + r0 + i;
        if (m >= M) continue;
#pragma unroll
        for (int j = 0; j < 8; j++) {
            int n = bn + c0 + j;
            if (n >= N) continue;
            float v = alpha * acc[i][j];
            if (has_bias) v += bias[n];
            if (relu) v = fmaxf(v, 0.f);
            if (has_res) v += Rb[(long long)m * ldr + n];
            Cp[(long long)m * ldc + n] = v;
        }
    }
}

// ---------------- positional features (one warp per position) ----------------
__global__ void pos_kernel(float* __restrict__ pos) {
    int row = blockIdx.x;                 // 0..3070
    int i   = threadIdx.x;                // 0..31 (n = F/6 = 32)
    float p  = (float)(row - (TT - 1));
    float ap = fabsf(p);
    float sg = (p > 0.f) ? 1.f : ((p < 0.f) ? -1.f : 0.f);

    // exponential decay
    double log2T = log(1536.0) / log(2.0);
    double hl    = exp2(3.0 + (double)i * (log2T - 3.0) / 31.0);
    float coef   = (float)(-0.6931471805599453 / hl);
    float fe     = expf(coef * ap);

    // central mask
    float width = (float)(exp2((double)(i + 1)) - 1.0);
    float fcm   = (width > ap) ? 1.f : 0.f;

    // gamma pdf
    double mean  = 48.0 * (double)(i + 1);            // linspace(48,1536,32)
    double stdv  = 24.0;                              // T/(2n)
    float conc   = (float)((mean/stdv)*(mean/stdv));
    float rate   = (float)(mean/(stdv*stdv));
    double lu    = (double)(conc - 1.f) * log((double)ap) - (double)rate * (double)ap; // ap=0 -> -inf -> exp 0
    double ln    = lgamma((double)conc) - (double)conc * log((double)rate);
    float prob   = (float)exp(lu - ln) + 1e-8f;

    float mx = prob;
#pragma unroll
    for (int o = 16; o > 0; o >>= 1) mx = fmaxf(mx, __shfl_xor_sync(0xffffffffu, mx, o));
    float fg = prob / mx;

    float* pr = pos + (size_t)row * FF;
    pr[      i] = fe;      pr[ 32 + i] = fcm;      pr[ 64 + i] = fg;
    pr[ 96 + i] = sg*fe;   pr[128 + i] = sg*fcm;   pr[160 + i] = sg*fg;
}

// ---------------- fused content+relative logits (with implicit rel-shift) ----------------
// logits[h,q,j] = (q+rw)·k[j]  +  (q+rr)·r_k[j - q + T - 1]
__global__ __launch_bounds__(256)
void logits_kernel(const float* __restrict__ q, const float* __restrict__ k,
                   const float* __restrict__ rk, const float* __restrict__ rwb,
                   const float* __restrict__ rrb, float* __restrict__ out)
{
    int h  = blockIdx.z;
    int q0 = blockIdx.y * 64, j0 = blockIdx.x * 64;
    int base = j0 - q0 + (TT - 1) - 63;   // band start (>= 0 always)

    __shared__ float sqw[64][33];
    __shared__ float sqr[64][33];
    __shared__ float sk [64][33];
    __shared__ float sb [128][33];

    int tid = threadIdx.x;
    int ty = tid >> 4, tx = tid & 15;
    int rr0 = ty * 4, cc0 = tx * 4;
    float acc[4][4];
#pragma unroll
    for (int i = 0; i < 4; i++)
#pragma unroll
        for (int j = 0; j < 4; j++) acc[i][j] = 0.f;

    for (int cb = 0; cb < HK; cb += 32) {
        for (int idx = tid; idx < 64 * 32; idx += 256) {
            int r = idx >> 5, kk = idx & 31;
            float qv = q[(size_t)(q0 + r) * QKC + h * HK + cb + kk];
            sqw[r][kk] = qv + rwb[h * HK + cb + kk];
            sqr[r][kk] = qv + rrb[h * HK + cb + kk];
            sk [r][kk] = k[(size_t)(j0 + r) * QKC + h * HK + cb + kk];
        }
        for (int idx = tid; idx < 128 * 32; idx += 256) {
            int r = idx >> 5, kk = idx & 31;
            int gr = base + r;
            sb[r][kk] = (gr < LL) ? rk[(size_t)gr * QKC + h * HK + cb + kk] : 0.f;
        }
        __syncthreads();

#pragma unroll 4
        for (int kk = 0; kk < 32; kk++) {
            float aw[4], ar[4], bk[4], bd[7];
#pragma unroll
            for (int i = 0; i < 4; i++) { aw[i] = sqw[rr0+i][kk]; ar[i] = sqr[rr0+i][kk]; }
#pragma unroll
            for (int j = 0; j < 4; j++) bk[j] = sk[cc0+j][kk];
            int db = cc0 - rr0 + 60;      // diag index for (j - i + 3) = 0
#pragma unroll
            for (int d = 0; d < 7; d++) bd[d] = sb[db + d][kk];
#pragma unroll
            for (int i = 0; i < 4; i++)
#pragma unroll
                for (int j = 0; j < 4; j++)
                    acc[i][j] += aw[i] * bk[j] + ar[i] * bd[j - i + 3];
        }
        __syncthreads();
    }

#pragma unroll
    for (int i = 0; i < 4; i++)
#pragma unroll
        for (int j = 0; j < 4; j++)
            out[((size_t)h * TT + q0 + rr0 + i) * TT + j0 + cc0 + j] = acc[i][j];
}

// ---------------- row softmax (in place) ----------------
__global__ void softmax_kernel(float* __restrict__ x) {
    size_t row = blockIdx.x;
    float* xr = x + row * TT;
    __shared__ float red[256];
    float m = -1e30f;
    for (int c = threadIdx.x; c < TT; c += 256) m = fmaxf(m, xr[c]);
    red[threadIdx.x] = m; __syncthreads();
    for (int st = 128; st > 0; st >>= 1) {
        if (threadIdx.x < st) red[threadIdx.x] = fmaxf(red[threadIdx.x], red[threadIdx.x+st]);
        __syncthreads();
    }
    m = red[0]; __syncthreads();
    float s = 0.f;
    for (int c = threadIdx.x; c < TT; c += 256) { float e = expf(xr[c] - m); xr[c] = e; s += e; }
    red[threadIdx.x] = s; __syncthreads();
    for (int st = 128; st > 0; st >>= 1) {
        if (threadIdx.x < st) red[threadIdx.x] += red[threadIdx.x+st];
        __syncthreads();
    }
    float inv = 1.f / red[0];
    for (int c = threadIdx.x; c < TT; c += 256) xr[c] *= inv;
}

// ---------------- host launch ----------------
extern "C" void kernel_launch(void* const* d_in, const int* in_sizes, int n_in,
                              void* d_out, int out_size) {
    const float* x     = (const float*)d_in[0];
    const float* ln1_g = (const float*)d_in[1];
    const float* ln1_b = (const float*)d_in[2];
    const float* ln2_g = (const float*)d_in[3];
    const float* ln2_b = (const float*)d_in[4];
    const float* Wq    = (const float*)d_in[5];
    const float* Wk    = (const float*)d_in[6];
    const float* Wv    = (const float*)d_in[7];
    const float* Wr    = (const float*)d_in[8];
    const float* Wo    = (const float*)d_in[9];
    const float* bo    = (const float*)d_in[10];
    const float* rwb   = (const float*)d_in[11];
    const float* rrb   = (const float*)d_in[12];
    const float* W1    = (const float*)d_in[13];
    const float* b1    = (const float*)d_in[14];
    const float* W2    = (const float*)d_in[15];
    const float* b2    = (const float*)d_in[16];
    float* out = (float*)d_out;

    float *xn, *q, *k, *v, *pos, *rk, *logits, *o, *y, *yn, *h1;
    cudaGetSymbolAddress((void**)&xn, g_xn);
    cudaGetSymbolAddress((void**)&q,  g_q);
    cudaGetSymbolAddress((void**)&k,  g_k);
    cudaGetSymbolAddress((void**)&v,  g_v);
    cudaGetSymbolAddress((void**)&pos, g_pos);
    cudaGetSymbolAddress((void**)&rk, g_rk);
    cudaGetSymbolAddress((void**)&logits, g_logits);
    cudaGetSymbolAddress((void**)&o,  g_o);
    cudaGetSymbolAddress((void**)&y,  g_y);
    cudaGetSymbolAddress((void**)&yn, g_yn);
    cudaGetSymbolAddress((void**)&h1, g_h1);

    // LN1
    ln_kernel<<<TT, 256>>>(x, ln1_g, ln1_b, xn);

    // Q (scaled by K^-0.5), K, V projections
    gemm_kernel<<<dim3(4,12,1), 256>>>(TT, QKC, CC, xn, CC, 0, Wq, QKC, 0, q, QKC, 0,
                                       nullptr, nullptr, 0, 0, 0.125f, 0);
    gemm_kernel<<<dim3(4,12,1), 256>>>(TT, QKC, CC, xn, CC, 0, Wk, QKC, 0, k, QKC, 0,
                                       nullptr, nullptr, 0, 0, 1.0f, 0);
    gemm_kernel<<<dim3(12,12,1), 256>>>(TT, CC, CC, xn, CC, 0, Wv, CC, 0, v, CC, 0,
                                        nullptr, nullptr, 0, 0, 1.0f, 0);

    // positional features + r_k projection
    pos_kernel<<<LL, 32>>>(pos);
    gemm_kernel<<<dim3(4,24,1), 256>>>(LL, QKC, FF, pos, FF, 0, Wr, QKC, 0, rk, QKC, 0,
                                       nullptr, nullptr, 0, 0, 1.0f, 0);

    // fused content + shifted-relative logits
    logits_kernel<<<dim3(24,24,HH), 256>>>(q, k, rk, rwb, rrb, logits);

    // softmax
    softmax_kernel<<<HH*TT, 256>>>(logits);

    // attn @ V (batched over heads; per-head column slices of v/o)
    gemm_kernel<<<dim3(2,12,HH), 256>>>(TT, HV, TT,
                                        logits, TT, (long long)TT*TT,
                                        v, CC, HV,
                                        o, CC, HV,
                                        nullptr, nullptr, 0, 0, 1.0f, 0);

    // output projection + bias + residual
    gemm_kernel<<<dim3(12,12,1), 256>>>(TT, CC, CC, o, CC, 0, Wo, CC, 0, y, CC, 0,
                                        bo, x, CC, 0, 1.0f, 0);

    // LN2 + MLP
    ln_kernel<<<TT, 256>>>(y, ln2_g, ln2_b, yn);
    gemm_kernel<<<dim3(24,12,1), 256>>>(TT, 2*CC, CC, yn, CC, 0, W1, 2*CC, 0, h1, 2*CC, 0,
                                        b1, nullptr, 0, 0, 1.0f, 1);
    gemm_kernel<<<dim3(12,12,1), 256>>>(TT, CC, 2*CC, h1, 2*CC, 0, W2, CC, 0, out, CC, 0,
                                        b2, y, CC, 0, 1.0f, 0);
}

// round 4
// speedup vs baseline: 2.0197x; 2.0197x over previous
#include <cuda_runtime.h>
#include <cuda_bf16.h>
#include <math.h>
#include <stdint.h>

#define TT 1536
#define CC 1536
#define HH 8
#define HK 64
#define HV 192
#define FF 192
#define QKC 512
#define LLP 3072          // padded 2T-1 (3071 -> 3072)

// ---------------- scratch (device globals; allocation-free) ----------------
__device__ float g_xn[TT*CC];
__device__ float g_q [TT*QKC];
__device__ float g_k [TT*QKC];
__device__ float g_v [TT*CC];
__device__ float g_vT[TT*CC];
__device__ float g_pos[LLP*FF];
__device__ float g_rk [LLP*QKC];
__device__ float g_content[HH*TT*TT];    // becomes attn in place
__device__ float g_rel[HH*TT*LLP];
__device__ float g_o [TT*CC];
__device__ float g_y [TT*CC];
__device__ float g_yn[TT*CC];
__device__ float g_h1[TT*2*CC];
__device__ float g_wqT[QKC*CC];
__device__ float g_wkT[QKC*CC];
__device__ float g_wvT[CC*CC];
__device__ float g_woT[CC*CC];
__device__ float g_w1T[2*CC*CC];
__device__ float g_w2T[CC*2*CC];
__device__ float g_wrT[QKC*FF];

// ---------------- helpers ----------------
__device__ __forceinline__ uint32_t pack_bf2(float a, float b) {
    __nv_bfloat162 t = __floats2bfloat162_rn(a, b);
    return *reinterpret_cast<uint32_t*>(&t);
}
__device__ __forceinline__ float bfr(float x) {
    return __bfloat162float(__float2bfloat16(x));
}
__device__ __forceinline__ void mma_bf16(float* c, const uint32_t* a, const uint32_t* b) {
    asm volatile("mma.sync.aligned.m16n8k16.row.col.f32.bf16.bf16.f32 "
        "{%0,%1,%2,%3},{%4,%5,%6,%7},{%8,%9},{%0,%1,%2,%3};"
        : "+f"(c[0]), "+f"(c[1]), "+f"(c[2]), "+f"(c[3])
        : "r"(a[0]), "r"(a[1]), "r"(a[2]), "r"(a[3]), "r"(b[0]), "r"(b[1]));
}

// smem regions (bytes): [rows][32 k] bf16, 72 B/row (64 data + 8 pad)
#define ROWB 72
#define SM_AH 0
#define SM_AL 9216
#define SM_BH 18432
#define SM_BL 27648
#define SM_TOT 36864

// ---------------- universal bf16x3 mma.sync GEMM ----------------
// C[M,N] = alpha * (A (+Abias)) @ B^T ; B stored [N,K] K-major.
// batch z: A+z*sA, AB+z*sAB, B+z*sB, C+z*sC, R+z*sR.
// M % 128 == 0, K % 32 == 0; N arbitrary (guarded).
__global__ __launch_bounds__(256)
void tgemm_kernel(int M, int N, int K,
                  const float* __restrict__ A, int lda, long long sA,
                  const float* __restrict__ AB, long long sAB,
                  const float* __restrict__ B, int ldb, long long sB,
                  float* __restrict__ Cp, int ldc, long long sC,
                  const float* __restrict__ bias,
                  const float* __restrict__ Rp, int ldr, long long sR,
                  float alpha, int relu)
{
    __shared__ char smem[SM_TOT];
    int tid = threadIdx.x;
    int wid = tid >> 5, lane = tid & 31;
    int grp = lane >> 2, tig = lane & 3;
    int wm = wid & 1, wn = wid >> 1;
    int z = blockIdx.z;
    A += (long long)z * sA;
    B += (long long)z * sB;
    Cp += (long long)z * sC;
    const float* Ab = AB ? AB + (long long)z * sAB : nullptr;
    const float* Rb = Rp ? Rp + (long long)z * sR : nullptr;
    int bm = blockIdx.y * 128, bn = blockIdx.x * 128;

    const int nch = K >> 5;
    const int lrow = tid >> 1;
    const int lcb  = (tid & 1) << 4;          // 0 or 16 (floats)
    const bool bvalid = (bn + lrow) < N;

    float4 pfA[4], pfB[4];

    // prologue: global-load chunk 0
    {
        const float* ap = A + (size_t)(bm + lrow) * lda + lcb;
#pragma unroll
        for (int i = 0; i < 4; i++) {
            pfA[i] = *(const float4*)(ap + i * 4);
            if (Ab) {
                float4 t = *(const float4*)(Ab + lcb + i * 4);
                pfA[i].x += t.x; pfA[i].y += t.y; pfA[i].z += t.z; pfA[i].w += t.w;
            }
        }
        const float* bp = B + (size_t)(bn + lrow) * ldb + lcb;
#pragma unroll
        for (int i = 0; i < 4; i++)
            pfB[i] = bvalid ? *(const float4*)(bp + i * 4) : make_float4(0, 0, 0, 0);
    }

    float acc[4][4][4];
#pragma unroll
    for (int a = 0; a < 4; a++)
#pragma unroll
        for (int b = 0; b < 4; b++)
#pragma unroll
            for (int r = 0; r < 4; r++) acc[a][b][r] = 0.f;

    char* sA_hi = smem + SM_AH; char* sA_lo = smem + SM_AL;
    char* sB_hi = smem + SM_BH; char* sB_lo = smem + SM_BL;

    for (int c = 0; c < nch; c++) {
        // store prefetched regs -> smem (split hi/lo)
        {
            uint32_t boff = (uint32_t)lrow * ROWB + ((uint32_t)lcb << 1);
#pragma unroll
            for (int i = 0; i < 4; i++) {
                float4 v = pfA[i];
                uint2 hw, lw;
                hw.x = pack_bf2(v.x, v.y);          hw.y = pack_bf2(v.z, v.w);
                lw.x = pack_bf2(v.x - bfr(v.x), v.y - bfr(v.y));
                lw.y = pack_bf2(v.z - bfr(v.z), v.w - bfr(v.w));
                *(uint2*)(sA_hi + boff + i * 8) = hw;
                *(uint2*)(sA_lo + boff + i * 8) = lw;
            }
#pragma unroll
            for (int i = 0; i < 4; i++) {
                float4 v = pfB[i];
                uint2 hw, lw;
                hw.x = pack_bf2(v.x, v.y);          hw.y = pack_bf2(v.z, v.w);
                lw.x = pack_bf2(v.x - bfr(v.x), v.y - bfr(v.y));
                lw.y = pack_bf2(v.z - bfr(v.z), v.w - bfr(v.w));
                *(uint2*)(sB_hi + boff + i * 8) = hw;
                *(uint2*)(sB_lo + boff + i * 8) = lw;
            }
        }
        __syncthreads();

        // prefetch next chunk
        if (c + 1 < nch) {
            int k0 = (c + 1) << 5;
            const float* ap = A + (size_t)(bm + lrow) * lda + k0 + lcb;
#pragma unroll
            for (int i = 0; i < 4; i++) {
                pfA[i] = *(const float4*)(ap + i * 4);
                if (Ab) {
                    float4 t = *(const float4*)(Ab + k0 + lcb + i * 4);
                    pfA[i].x += t.x; pfA[i].y += t.y; pfA[i].z += t.z; pfA[i].w += t.w;
                }
            }
            const float* bp = B + (size_t)(bn + lrow) * ldb + k0 + lcb;
#pragma unroll
            for (int i = 0; i < 4; i++)
                pfB[i] = bvalid ? *(const float4*)(bp + i * 4) : make_float4(0, 0, 0, 0);
        }

        // compute: 2 k-steps of m16n8k16
#pragma unroll
        for (int ks = 0; ks < 2; ks++) {
            int kc = (ks << 4) + (tig << 1);
            uint32_t ahf[4][4], alf[4][4];
#pragma unroll
            for (int ms = 0; ms < 4; ms++) {
                uint32_t r0 = (uint32_t)(wm * 64 + ms * 16 + grp);
                uint32_t o00 = r0 * ROWB + (kc << 1);
                ahf[ms][0] = *(const uint32_t*)(sA_hi + o00);
                ahf[ms][1] = *(const uint32_t*)(sA_hi + o00 + 8 * ROWB);
                ahf[ms][2] = *(const uint32_t*)(sA_hi + o00 + 16);
                ahf[ms][3] = *(const uint32_t*)(sA_hi + o00 + 8 * ROWB + 16);
                alf[ms][0] = *(const uint32_t*)(sA_lo + o00);
                alf[ms][1] = *(const uint32_t*)(sA_lo + o00 + 8 * ROWB);
                alf[ms][2] = *(const uint32_t*)(sA_lo + o00 + 16);
                alf[ms][3] = *(const uint32_t*)(sA_lo + o00 + 8 * ROWB + 16);
            }
            uint32_t bhf[4][2], blf[4][2];
#pragma unroll
            for (int ns = 0; ns < 4; ns++) {
                uint32_t c0 = (uint32_t)(wn * 32 + ns * 8 + grp);
                uint32_t o0 = c0 * ROWB + (kc << 1);
                bhf[ns][0] = *(const uint32_t*)(sB_hi + o0);
                bhf[ns][1] = *(const uint32_t*)(sB_hi + o0 + 16);
                blf[ns][0] = *(const uint32_t*)(sB_lo + o0);
                blf[ns][1] = *(const uint32_t*)(sB_lo + o0 + 16);
            }
#pragma unroll
            for (int ms = 0; ms < 4; ms++)
#pragma unroll
                for (int ns = 0; ns < 4; ns++) {
                    mma_bf16(acc[ms][ns], ahf[ms], bhf[ns]);
                    mma_bf16(acc[ms][ns], ahf[ms], blf[ns]);
                    mma_bf16(acc[ms][ns], alf[ms], bhf[ns]);
                }
        }
        __syncthreads();
    }

    // epilogue
    const bool has_bias = (bias != nullptr);
#pragma unroll
    for (int ms = 0; ms < 4; ms++) {
        int row0 = bm + wm * 64 + ms * 16 + grp;
#pragma unroll
        for (int ns = 0; ns < 4; ns++) {
            int col = bn + wn * 32 + ns * 8 + (tig << 1);
            if (col >= N) continue;
#pragma unroll
            for (int h = 0; h < 2; h++) {           // h=0 -> c0,c1 ; h=1 -> c2,c3
                int m = row0 + h * 8;
                float v0 = alpha * acc[ms][ns][h * 2 + 0];
                float v1 = alpha * acc[ms][ns][h * 2 + 1];
                if (has_bias) { v0 += bias[col]; v1 += bias[col + 1]; }
                if (relu) { v0 = fmaxf(v0, 0.f); v1 = fmaxf(v1, 0.f); }
                if (Rb) {
                    const float* rp = Rb + (size_t)m * ldr + col;
                    v0 += rp[0]; v1 += rp[1];
                }
                *(float2*)(Cp + (size_t)m * ldc + col) = make_float2(v0, v1);
            }
        }
    }
}

// ---------------- LayerNorm ----------------
__global__ void ln_kernel(const float* __restrict__ x, const float* __restrict__ g,
                          const float* __restrict__ b, float* __restrict__ out) {
    int row = blockIdx.x;
    const float* xr = x + (size_t)row * CC;
    float s = 0.f, sq = 0.f;
    for (int c = threadIdx.x; c < CC; c += blockDim.x) { float v = xr[c]; s += v; sq += v * v; }
    __shared__ float rs[256], rq[256];
    rs[threadIdx.x] = s; rq[threadIdx.x] = sq; __syncthreads();
    for (int st = 128; st > 0; st >>= 1) {
        if (threadIdx.x < st) { rs[threadIdx.x] += rs[threadIdx.x + st]; rq[threadIdx.x] += rq[threadIdx.x + st]; }
        __syncthreads();
    }
    float mean = rs[0] / CC;
    float var  = rq[0] / CC - mean * mean;
    float rstd = rsqrtf(var + 1e-3f);
    for (int c = threadIdx.x; c < CC; c += blockDim.x)
        out[(size_t)row * CC + c] = (xr[c] - mean) * rstd * g[c] + b[c];
}

// ---------------- transpose: in[R,C] -> out[C,R] ----------------
__global__ void transpose_kernel(const float* __restrict__ in, float* __restrict__ out,
                                 int R, int Cc) {
    __shared__ float t[32][33];
    int bx = blockIdx.x * 32, by = blockIdx.y * 32;
    int x = bx + threadIdx.x;
    for (int i = threadIdx.y; i < 32; i += 8)
        t[i][threadIdx.x] = in[(size_t)(by + i) * Cc + x];
    __syncthreads();
    int xo = by + threadIdx.x;
    for (int i = threadIdx.y; i < 32; i += 8)
        out[(size_t)(bx + i) * R + xo] = t[threadIdx.x][i];
}

// ---------------- positional features ----------------
__global__ void pos_kernel(float* __restrict__ pos) {
    int row = blockIdx.x;                 // 0..3071 (row 3071 = pad, never read)
    int i   = threadIdx.x;                // 0..31
    float p  = (float)(row - (TT - 1));
    float ap = fabsf(p);
    float sg = (p > 0.f) ? 1.f : ((p < 0.f) ? -1.f : 0.f);

    double log2T = log(1536.0) / log(2.0);
    double hl    = exp2(3.0 + (double)i * (log2T - 3.0) / 31.0);
    float coef   = (float)(-0.6931471805599453 / hl);
    float fe     = expf(coef * ap);

    float width = (float)(exp2((double)(i + 1)) - 1.0);
    float fcm   = (width > ap) ? 1.f : 0.f;

    double mean = 48.0 * (double)(i + 1);
    double stdv = 24.0;
    float conc  = (float)((mean / stdv) * (mean / stdv));
    float rate  = (float)(mean / (stdv * stdv));
    double lu   = (double)(conc - 1.f) * log((double)ap) - (double)rate * (double)ap;
    double ln   = lgamma((double)conc) - (double)conc * log((double)rate);
    float prob  = (float)exp(lu - ln) + 1e-8f;

    float mx = prob;
#pragma unroll
    for (int o = 16; o > 0; o >>= 1) mx = fmaxf(mx, __shfl_xor_sync(0xffffffffu, mx, o));
    float fg = prob / mx;

    float* pr = pos + (size_t)row * FF;
    pr[      i] = fe;      pr[ 32 + i] = fcm;      pr[ 64 + i] = fg;
    pr[ 96 + i] = sg * fe; pr[128 + i] = sg * fcm; pr[160 + i] = sg * fg;
}

// ---------------- fused shift + softmax: attn = softmax(content + shift(rel)) in place ----------------
__global__ void softmax_merge_kernel(float* __restrict__ cont, const float* __restrict__ rel) {
    int row = blockIdx.x;                 // h*T + q
    int q = row % TT;
    float* cr = cont + (size_t)row * TT;
    const float* rr = rel + (size_t)row * LLP + (TT - 1 - q);
    __shared__ float red[256];
    float m = -1e30f;
    for (int j = threadIdx.x; j < TT; j += 256) m = fmaxf(m, cr[j] + rr[j]);
    red[threadIdx.x] = m; __syncthreads();
    for (int st = 128; st > 0; st >>= 1) {
        if (threadIdx.x < st) red[threadIdx.x] = fmaxf(red[threadIdx.x], red[threadIdx.x + st]);
        __syncthreads();
    }
    m = red[0]; __syncthreads();
    float s = 0.f;
    for (int j = threadIdx.x; j < TT; j += 256) {
        float e = expf(cr[j] + rr[j] - m);
        cr[j] = e; s += e;
    }
    red[threadIdx.x] = s; __syncthreads();
    for (int st = 128; st > 0; st >>= 1) {
        if (threadIdx.x < st) red[threadIdx.x] += red[threadIdx.x + st];
        __syncthreads();
    }
    float inv = 1.f / red[0];
    for (int j = threadIdx.x; j < TT; j += 256) cr[j] *= inv;
}

// ---------------- host launch ----------------
extern "C" void kernel_launch(void* const* d_in, const int* in_sizes, int n_in,
                              void* d_out, int out_size) {
    const float* x     = (const float*)d_in[0];
    const float* ln1_g = (const float*)d_in[1];
    const float* ln1_b = (const float*)d_in[2];
    const float* ln2_g = (const float*)d_in[3];
    const float* ln2_b = (const float*)d_in[4];
    const float* Wq    = (const float*)d_in[5];
    const float* Wk    = (const float*)d_in[6];
    const float* Wv    = (const float*)d_in[7];
    const float* Wr    = (const float*)d_in[8];
    const float* Wo    = (const float*)d_in[9];
    const float* bo    = (const float*)d_in[10];
    const float* rwb   = (const float*)d_in[11];
    const float* rrb   = (const float*)d_in[12];
    const float* W1    = (const float*)d_in[13];
    const float* b1    = (const float*)d_in[14];
    const float* W2    = (const float*)d_in[15];
    const float* b2    = (const float*)d_in[16];
    float* out = (float*)d_out;

    float *xn, *q, *k, *v, *vT, *pos, *rk, *cont, *rel, *o, *y, *yn, *h1;
    float *wqT, *wkT, *wvT, *woT, *w1T, *w2T, *wrT;
    cudaGetSymbolAddress((void**)&xn, g_xn);
    cudaGetSymbolAddress((void**)&q,  g_q);
    cudaGetSymbolAddress((void**)&k,  g_k);
    cudaGetSymbolAddress((void**)&v,  g_v);
    cudaGetSymbolAddress((void**)&vT, g_vT);
    cudaGetSymbolAddress((void**)&pos, g_pos);
    cudaGetSymbolAddress((void**)&rk, g_rk);
    cudaGetSymbolAddress((void**)&cont, g_content);
    cudaGetSymbolAddress((void**)&rel, g_rel);
    cudaGetSymbolAddress((void**)&o,  g_o);
    cudaGetSymbolAddress((void**)&y,  g_y);
    cudaGetSymbolAddress((void**)&yn, g_yn);
    cudaGetSymbolAddress((void**)&h1, g_h1);
    cudaGetSymbolAddress((void**)&wqT, g_wqT);
    cudaGetSymbolAddress((void**)&wkT, g_wkT);
    cudaGetSymbolAddress((void**)&wvT, g_wvT);
    cudaGetSymbolAddress((void**)&woT, g_woT);
    cudaGetSymbolAddress((void**)&w1T, g_w1T);
    cudaGetSymbolAddress((void**)&w2T, g_w2T);
    cudaGetSymbolAddress((void**)&wrT, g_wrT);

    dim3 tb(32, 8);

    // LN1 + weight transposes
    ln_kernel<<<TT, 256>>>(x, ln1_g, ln1_b, xn);
    transpose_kernel<<<dim3(QKC/32, CC/32), tb>>>(Wq, wqT, CC, QKC);
    transpose_kernel<<<dim3(QKC/32, CC/32), tb>>>(Wk, wkT, CC, QKC);
    transpose_kernel<<<dim3(CC/32, CC/32), tb>>>(Wv, wvT, CC, CC);
    transpose_kernel<<<dim3(QKC/32, FF/32), tb>>>(Wr, wrT, FF, QKC);
    transpose_kernel<<<dim3(CC/32, CC/32), tb>>>(Wo, woT, CC, CC);
    transpose_kernel<<<dim3(2*CC/32, CC/32), tb>>>(W1, w1T, CC, 2*CC);
    transpose_kernel<<<dim3(CC/32, 2*CC/32), tb>>>(W2, w2T, 2*CC, CC);

    // projections (q scaled by K^-0.5)
    tgemm_kernel<<<dim3(QKC/128, TT/128, 1), 256>>>(
        TT, QKC, CC, xn, CC, 0, nullptr, 0, wqT, CC, 0, q, QKC, 0,
        nullptr, nullptr, 0, 0, 0.125f, 0);
    tgemm_kernel<<<dim3(QKC/128, TT/128, 1), 256>>>(
        TT, QKC, CC, xn, CC, 0, nullptr, 0, wkT, CC, 0, k, QKC, 0,
        nullptr, nullptr, 0, 0, 1.0f, 0);
    tgemm_kernel<<<dim3(CC/128, TT/128, 1), 256>>>(
        TT, CC, CC, xn, CC, 0, nullptr, 0, wvT, CC, 0, v, CC, 0,
        nullptr, nullptr, 0, 0, 1.0f, 0);

    // positional features + r_k projection
    pos_kernel<<<LLP, 32>>>(pos);
    tgemm_kernel<<<dim3(QKC/128, LLP/128, 1), 256>>>(
        LLP, QKC, FF, pos, FF, 0, nullptr, 0, wrT, FF, 0, rk, QKC, 0,
        nullptr, nullptr, 0, 0, 1.0f, 0);

    // content[h] = (q_h + rw_h) @ k_h^T
    tgemm_kernel<<<dim3(TT/128, TT/128, HH), 256>>>(
        TT, TT, HK, q, QKC, HK, rwb, HK, k, QKC, HK,
        cont, TT, (long long)TT*TT, nullptr, nullptr, 0, 0, 1.0f, 0);

    // rel[h] = (q_h + rr_h) @ rk_h^T
    tgemm_kernel<<<dim3(LLP/128, TT/128, HH), 256>>>(
        TT, LLP, HK, q, QKC, HK, rrb, HK, rk, QKC, HK,
        rel, LLP, (long long)TT*LLP, nullptr, nullptr, 0, 0, 1.0f, 0);

    // fused relative-shift + softmax
    softmax_merge_kernel<<<HH*TT, 256>>>(cont, rel);

    // attn @ V
    transpose_kernel<<<dim3(CC/32, CC/32), tb>>>(v, vT, CC, CC);
    tgemm_kernel<<<dim3(2, TT/128, HH), 256>>>(
        TT, HV, TT, cont, TT, (long long)TT*TT, nullptr, 0,
        vT, TT, (long long)HV*TT, o, CC, HV,
        nullptr, nullptr, 0, 0, 1.0f, 0);

    // output projection + bias + residual
    tgemm_kernel<<<dim3(CC/128, TT/128, 1), 256>>>(
        TT, CC, CC, o, CC, 0, nullptr, 0, woT, CC, 0, y, CC, 0,
        bo, x, CC, 0, 1.0f, 0);

    // LN2 + MLP
    ln_kernel<<<TT, 256>>>(y, ln2_g, ln2_b, yn);
    tgemm_kernel<<<dim3(2*CC/128, TT/128, 1), 256>>>(
        TT, 2*CC, CC, yn, CC, 0, nullptr, 0, w1T, CC, 0, h1, 2*CC, 0,
        b1, nullptr, 0, 0, 1.0f, 1);
    tgemm_kernel<<<dim3(CC/128, TT/128, 1), 256>>>(
        TT, CC, 2*CC, h1, 2*CC, 0, nullptr, 0, w2T, 2*CC, 0, out, CC, 0,
        b2, y, CC, 0, 1.0f, 0);
}

// round 5
// speedup vs baseline: 2.7757x; 1.3743x over previous
#include <cuda_runtime.h>
#include <cuda_bf16.h>
#include <math.h>
#include <stdint.h>

#define TT 1536
#define CC 1536
#define HH 8
#define HK 64
#define HV 192
#define FF 192
#define QKC 512
#define LLP 3072
typedef __nv_bfloat16 bf16;

// ---------------- scratch ----------------
__device__ bf16 g_xn_h[TT*CC],  g_xn_l[TT*CC];
__device__ bf16 g_wq_h[QKC*CC], g_wq_l[QKC*CC];
__device__ bf16 g_wk_h[QKC*CC], g_wk_l[QKC*CC];
__device__ bf16 g_wv_h[CC*CC],  g_wv_l[CC*CC];
__device__ bf16 g_wr_h[QKC*FF], g_wr_l[QKC*FF];
__device__ bf16 g_wo_h[CC*CC],  g_wo_l[CC*CC];
__device__ bf16 g_w1_h[2*CC*CC],g_w1_l[2*CC*CC];
__device__ bf16 g_w2_h[CC*2*CC],g_w2_l[CC*2*CC];
__device__ float g_qf[TT*QKC];
__device__ bf16 g_qw_h[TT*QKC], g_qw_l[TT*QKC];
__device__ bf16 g_qr_h[TT*QKC], g_qr_l[TT*QKC];
__device__ bf16 g_k_h[TT*QKC],  g_k_l[TT*QKC];
__device__ float g_vf[TT*CC];
__device__ bf16 g_vT_h[CC*TT],  g_vT_l[CC*TT];
__device__ bf16 g_pos_h[LLP*FF],g_pos_l[LLP*FF];
__device__ bf16 g_rk_h[LLP*QKC],g_rk_l[LLP*QKC];
__device__ float g_cont[HH*TT*TT];
__device__ float g_rel[(size_t)HH*TT*LLP];
__device__ bf16 g_at_h[HH*TT*TT], g_at_l[HH*TT*TT];
__device__ bf16 g_o_h[TT*CC],   g_o_l[TT*CC];
__device__ float g_y[TT*CC];
__device__ bf16 g_yn_h[TT*CC],  g_yn_l[TT*CC];
__device__ bf16 g_h1_h[TT*2*CC],g_h1_l[TT*2*CC];

// ---------------- helpers ----------------
__device__ __forceinline__ uint32_t smem_u32(const void* p) {
    uint32_t a;
    asm("{ .reg .u64 t; cvta.to.shared.u64 t, %1; cvt.u32.u64 %0, t; }" : "=r"(a) : "l"(p));
    return a;
}
__device__ __forceinline__ void mma_bf16(float* c, const uint32_t* a, const uint32_t* b) {
    asm volatile("mma.sync.aligned.m16n8k16.row.col.f32.bf16.bf16.f32 "
        "{%0,%1,%2,%3},{%4,%5,%6,%7},{%8,%9},{%0,%1,%2,%3};"
        : "+f"(c[0]), "+f"(c[1]), "+f"(c[2]), "+f"(c[3])
        : "r"(a[0]), "r"(a[1]), "r"(a[2]), "r"(a[3]), "r"(b[0]), "r"(b[1]));
}
__device__ __forceinline__ void ldsm4(uint32_t* r, uint32_t addr) {
    asm volatile("ldmatrix.sync.aligned.m8n8.x4.shared.b16 {%0,%1,%2,%3}, [%4];"
        : "=r"(r[0]), "=r"(r[1]), "=r"(r[2]), "=r"(r[3]) : "r"(addr));
}
__device__ __forceinline__ void cpasync16(uint32_t dst, const void* src, uint32_t sz) {
    asm volatile("cp.async.ca.shared.global [%0], [%1], 16, %2;"
                 :: "r"(dst), "l"(src), "r"(sz) : "memory");
}
__device__ __forceinline__ void cp_commit() { asm volatile("cp.async.commit_group;" ::: "memory"); }
__device__ __forceinline__ void cp_wait1()  { asm volatile("cp.async.wait_group 1;" ::: "memory"); }
__device__ __forceinline__ uint32_t pack_bf2(float a, float b) {
    __nv_bfloat162 t = __floats2bfloat162_rn(a, b);
    return *reinterpret_cast<uint32_t*>(&t);
}
__device__ __forceinline__ float bfr(float x) { return __bfloat162float(__float2bfloat16(x)); }
__device__ __forceinline__ void split_bf(float v, bf16& h, bf16& l) {
    h = __float2bfloat16(v);
    l = __float2bfloat16(v - __bfloat162float(h));
}

// smem stage layout: 80B padded rows
#define ROWB 80
#define STG_AH 0
#define STG_AL 10240
#define STG_BH 20480
#define STG_BL 30720
#define STG_SZ 40960
#define SM_TOT (2*STG_SZ)

// ---------------- bf16x3 mma.sync GEMM ----------------
// C = alpha*A@B^T (+bias)(relu)(+res);  A[M,K], B[N,K] row-major, both hi/lo.
// out: Cf fp32 OR (Ch,Cl) bf16-split.  win: bn = (11 - by + bx)*128.
__global__ __launch_bounds__(256, 2)
void tgemm_kernel(int M, int N, int K,
                  const bf16* __restrict__ Ah, const bf16* __restrict__ Al, int lda, long long sA,
                  const bf16* __restrict__ Bh, const bf16* __restrict__ Bl, int ldb, long long sB,
                  float* __restrict__ Cf, bf16* __restrict__ Ch, bf16* __restrict__ Cl,
                  int ldc, long long sC,
                  const float* __restrict__ bias,
                  const float* __restrict__ Rp, int ldr, long long sR,
                  float alpha, int relu, int win)
{
    extern __shared__ char smem[];
    uint32_t sbase = smem_u32(smem);
    int tid = threadIdx.x, wid = tid >> 5, lane = tid & 31;
    int grp = lane >> 2, tig = lane & 3;
    int wm = wid & 1, wn = wid >> 1;
    int z = blockIdx.z;
    Ah += (long long)z * sA;  Al += (long long)z * sA;
    Bh += (long long)z * sB;  Bl += (long long)z * sB;
    const float* Rb = Rp ? Rp + (long long)z * sR : nullptr;
    int bm = blockIdx.y * 128;
    int bn = win ? (11 - blockIdx.y + blockIdx.x) * 128 : blockIdx.x * 128;

    const int nch = K >> 5;
    // staging map: 2 threads per row, each thread 2 16B segs per matrix
    const int sr = tid >> 1;
    const int ss = (tid & 1) * 2;
    const bool bval = (bn + sr) < N;
    const uint32_t bvsz = bval ? 16u : 0u;

    // ldmatrix lane offsets
    const uint32_t lA = (uint32_t)(lane & 15) * ROWB + (uint32_t)(lane >> 4) * 16;
    const uint32_t lB = ((uint32_t)((lane >> 4) * 8 + (lane & 7))) * ROWB + (uint32_t)((lane >> 3) & 1) * 16;

    float acc[4][4][4];
#pragma unroll
    for (int a = 0; a < 4; a++)
#pragma unroll
        for (int b = 0; b < 4; b++)
#pragma unroll
            for (int r = 0; r < 4; r++) acc[a][b][r] = 0.f;

    // prologue: stages 0,1
#pragma unroll
    for (int s = 0; s < 2; s++) {
        if (s < nch) {
            int k0 = s << 5;
            uint32_t st = sbase + s * STG_SZ + sr * ROWB + ss * 16;
            const bf16* a0 = Ah + (size_t)(bm + sr) * lda + k0 + ss * 8;
            const bf16* a1 = Al + (size_t)(bm + sr) * lda + k0 + ss * 8;
            const bf16* b0 = Bh + (size_t)(bn + sr) * ldb + k0 + ss * 8;
            const bf16* b1 = Bl + (size_t)(bn + sr) * ldb + k0 + ss * 8;
#pragma unroll
            for (int i = 0; i < 2; i++) {
                cpasync16(st + STG_AH + i * 16, a0 + i * 8, 16);
                cpasync16(st + STG_AL + i * 16, a1 + i * 8, 16);
                cpasync16(st + STG_BH + i * 16, b0 + i * 8, bvsz);
                cpasync16(st + STG_BL + i * 16, b1 + i * 8, bvsz);
            }
        }
        cp_commit();
    }

    for (int c = 0; c < nch; c++) {
        cp_wait1();
        __syncthreads();
        uint32_t stg = sbase + (c & 1) * STG_SZ;
#pragma unroll
        for (int ks = 0; ks < 2; ks++) {
            uint32_t kb = ks * 32;
            uint32_t bh[2][4], bl[2][4];
#pragma unroll
            for (int p = 0; p < 2; p++) {
                uint32_t ba = stg + (uint32_t)(wn * 32 + p * 16) * ROWB + kb + lB;
                ldsm4(bh[p], ba + STG_BH);
                ldsm4(bl[p], ba + STG_BL);
            }
#pragma unroll
            for (int ms = 0; ms < 4; ms++) {
                uint32_t aa = stg + (uint32_t)(wm * 64 + ms * 16) * ROWB + kb + lA;
                uint32_t ah[4], al[4];
                ldsm4(ah, aa + STG_AH);
                ldsm4(al, aa + STG_AL);
#pragma unroll
                for (int ns = 0; ns < 4; ns++) {
                    uint32_t* bhp = &bh[ns >> 1][(ns & 1) * 2];
                    uint32_t* blp = &bl[ns >> 1][(ns & 1) * 2];
                    mma_bf16(acc[ms][ns], ah, bhp);
                    mma_bf16(acc[ms][ns], ah, blp);
                    mma_bf16(acc[ms][ns], al, bhp);
                }
            }
        }
        __syncthreads();
        if (c + 2 < nch) {
            int k0 = (c + 2) << 5;
            uint32_t st = sbase + (c & 1) * STG_SZ + sr * ROWB + ss * 16;
            const bf16* a0 = Ah + (size_t)(bm + sr) * lda + k0 + ss * 8;
            const bf16* a1 = Al + (size_t)(bm + sr) * lda + k0 + ss * 8;
            const bf16* b0 = Bh + (size_t)(bn + sr) * ldb + k0 + ss * 8;
            const bf16* b1 = Bl + (size_t)(bn + sr) * ldb + k0 + ss * 8;
#pragma unroll
            for (int i = 0; i < 2; i++) {
                cpasync16(st + STG_AH + i * 16, a0 + i * 8, 16);
                cpasync16(st + STG_AL + i * 16, a1 + i * 8, 16);
                cpasync16(st + STG_BH + i * 16, b0 + i * 8, bvsz);
                cpasync16(st + STG_BL + i * 16, b1 + i * 8, bvsz);
            }
        }
        cp_commit();
    }

    // epilogue
    Cf = Cf ? Cf + (long long)z * sC : nullptr;
    Ch = Ch ? Ch + (long long)z * sC : nullptr;
    Cl = Cl ? Cl + (long long)z * sC : nullptr;
    const bool has_bias = (bias != nullptr);
#pragma unroll
    for (int ms = 0; ms < 4; ms++) {
        int row0 = bm + wm * 64 + ms * 16 + grp;
#pragma unroll
        for (int ns = 0; ns < 4; ns++) {
            int col = bn + wn * 32 + ns * 8 + (tig << 1);
            if (col >= N) continue;
#pragma unroll
            for (int h = 0; h < 2; h++) {
                int m = row0 + h * 8;
                float v0 = alpha * acc[ms][ns][h * 2 + 0];
                float v1 = alpha * acc[ms][ns][h * 2 + 1];
                if (has_bias) { v0 += bias[col]; v1 += bias[col + 1]; }
                if (relu) { v0 = fmaxf(v0, 0.f); v1 = fmaxf(v1, 0.f); }
                if (Cf) {
                    if (Rb) {
                        const float* rp = Rb + (size_t)m * ldr + col;
                        v0 += rp[0]; v1 += rp[1];
                    }
                    *(float2*)(Cf + (size_t)m * ldc + col) = make_float2(v0, v1);
                } else {
                    uint32_t hw = pack_bf2(v0, v1);
                    uint32_t lw = pack_bf2(v0 - bfr(v0), v1 - bfr(v1));
                    *(uint32_t*)(Ch + (size_t)m * ldc + col) = hw;
                    *(uint32_t*)(Cl + (size_t)m * ldc + col) = lw;
                }
            }
        }
    }
}

// ---------------- LayerNorm -> bf16 hi/lo ----------------
__global__ void ln_kernel(const float* __restrict__ x, const float* __restrict__ g,
                          const float* __restrict__ b, bf16* __restrict__ oh, bf16* __restrict__ ol) {
    int row = blockIdx.x;
    const float* xr = x + (size_t)row * CC;
    float s = 0.f, sq = 0.f;
    for (int c = threadIdx.x; c < CC; c += blockDim.x) { float v = xr[c]; s += v; sq += v * v; }
    __shared__ float rs[256], rq[256];
    rs[threadIdx.x] = s; rq[threadIdx.x] = sq; __syncthreads();
    for (int st = 128; st > 0; st >>= 1) {
        if (threadIdx.x < st) { rs[threadIdx.x] += rs[threadIdx.x + st]; rq[threadIdx.x] += rq[threadIdx.x + st]; }
        __syncthreads();
    }
    float mean = rs[0] / CC;
    float var  = rq[0] / CC - mean * mean;
    float rstd = rsqrtf(var + 1e-3f);
    for (int c = threadIdx.x; c < CC; c += blockDim.x) {
        float v = (xr[c] - mean) * rstd * g[c] + b[c];
        bf16 h, l; split_bf(v, h, l);
        oh[(size_t)row * CC + c] = h;
        ol[(size_t)row * CC + c] = l;
    }
}

// ---------------- transpose+convert: in fp32 [R,C] -> hi/lo [C,R] ----------------
__global__ void cvtT_kernel(const float* __restrict__ in, bf16* __restrict__ oh,
                            bf16* __restrict__ ol, int R, int Cc) {
    __shared__ float t[32][33];
    int bx = blockIdx.x * 32, by = blockIdx.y * 32;
    int x = bx + threadIdx.x;
    for (int i = threadIdx.y; i < 32; i += 8)
        t[i][threadIdx.x] = in[(size_t)(by + i) * Cc + x];
    __syncthreads();
    int xo = by + threadIdx.x;
    for (int i = threadIdx.y; i < 32; i += 8) {
        float v = t[threadIdx.x][i];
        bf16 h, l; split_bf(v, h, l);
        oh[(size_t)(bx + i) * R + xo] = h;
        ol[(size_t)(bx + i) * R + xo] = l;
    }
}

// ---------------- convert with column bias ----------------
__global__ void cvtb_kernel(const float* __restrict__ in, const float* __restrict__ bias,
                            bf16* __restrict__ oh, bf16* __restrict__ ol, int n, int ld) {
    int i = blockIdx.x * 256 + threadIdx.x;
    if (i >= n) return;
    float v = in[i] + bias[i % ld];
    bf16 h, l; split_bf(v, h, l);
    oh[i] = h; ol[i] = l;
}

// ---------------- positional features -> bf16 hi/lo ----------------
__global__ void pos_kernel(bf16* __restrict__ oh, bf16* __restrict__ ol) {
    int row = blockIdx.x;
    int i   = threadIdx.x;
    float p  = (float)(row - (TT - 1));
    float ap = fabsf(p);
    float sg = (p > 0.f) ? 1.f : ((p < 0.f) ? -1.f : 0.f);

    double log2T = log(1536.0) / log(2.0);
    double hl    = exp2(3.0 + (double)i * (log2T - 3.0) / 31.0);
    float coef   = (float)(-0.6931471805599453 / hl);
    float fe     = expf(coef * ap);

    float width = (float)(exp2((double)(i + 1)) - 1.0);
    float fcm   = (width > ap) ? 1.f : 0.f;

    double mean = 48.0 * (double)(i + 1);
    double stdv = 24.0;
    float conc  = (float)((mean / stdv) * (mean / stdv));
    float rate  = (float)(mean / (stdv * stdv));
    double lu   = (double)(conc - 1.f) * log((double)ap) - (double)rate * (double)ap;
    double lnn  = lgamma((double)conc) - (double)conc * log((double)rate);
    float prob  = (float)exp(lu - lnn) + 1e-8f;

    float mx = prob;
#pragma unroll
    for (int o = 16; o > 0; o >>= 1) mx = fmaxf(mx, __shfl_xor_sync(0xffffffffu, mx, o));
    float fg = prob / mx;

    float vals[6] = { fe, fcm, fg, sg * fe, sg * fcm, sg * fg };
    size_t base = (size_t)row * FF;
#pragma unroll
    for (int c = 0; c < 6; c++) {
        bf16 h, l; split_bf(vals[c], h, l);
        oh[base + c * 32 + i] = h;
        ol[base + c * 32 + i] = l;
    }
}

// ---------------- fused shift + softmax -> attn bf16 hi/lo ----------------
__global__ void softmax_merge_kernel(const float* __restrict__ cont, const float* __restrict__ rel,
                                     bf16* __restrict__ ah, bf16* __restrict__ al) {
    int row = blockIdx.x;
    int q = row % TT;
    const float* cr = cont + (size_t)row * TT;
    const float* rr = rel + (size_t)row * LLP + (TT - 1 - q);
    __shared__ float red[256];
    float m = -1e30f;
    for (int j = threadIdx.x; j < TT; j += 256) m = fmaxf(m, cr[j] + rr[j]);
    red[threadIdx.x] = m; __syncthreads();
    for (int st = 128; st > 0; st >>= 1) {
        if (threadIdx.x < st) red[threadIdx.x] = fmaxf(red[threadIdx.x], red[threadIdx.x + st]);
        __syncthreads();
    }
    m = red[0]; __syncthreads();
    float s = 0.f;
    __shared__ float ebuf[TT];
    for (int j = threadIdx.x; j < TT; j += 256) {
        float e = expf(cr[j] + rr[j] - m);
        ebuf[j] = e; s += e;
    }
    red[threadIdx.x] = s; __syncthreads();
    for (int st = 128; st > 0; st >>= 1) {
        if (threadIdx.x < st) red[threadIdx.x] += red[threadIdx.x + st];
        __syncthreads();
    }
    float inv = 1.f / red[0];
    for (int j = threadIdx.x; j < TT; j += 256) {
        float v = ebuf[j] * inv;
        bf16 h, l; split_bf(v, h, l);
        ah[(size_t)row * TT + j] = h;
        al[(size_t)row * TT + j] = l;
    }
}

// ---------------- host launch ----------------
extern "C" void kernel_launch(void* const* d_in, const int* in_sizes, int n_in,
                              void* d_out, int out_size) {
    const float* x     = (const float*)d_in[0];
    const float* ln1_g = (const float*)d_in[1];
    const float* ln1_b = (const float*)d_in[2];
    const float* ln2_g = (const float*)d_in[3];
    const float* ln2_b = (const float*)d_in[4];
    const float* Wq    = (const float*)d_in[5];
    const float* Wk    = (const float*)d_in[6];
    const float* Wv    = (const float*)d_in[7];
    const float* Wr    = (const float*)d_in[8];
    const float* Wo    = (const float*)d_in[9];
    const float* bo    = (const float*)d_in[10];
    const float* rwb   = (const float*)d_in[11];
    const float* rrb   = (const float*)d_in[12];
    const float* W1    = (const float*)d_in[13];
    const float* b1    = (const float*)d_in[14];
    const float* W2    = (const float*)d_in[15];
    const float* b2    = (const float*)d_in[16];
    float* out = (float*)d_out;

#define GA(sym, ty) ({ void* p_; cudaGetSymbolAddress(&p_, sym); (ty*)p_; })
    bf16 *xnh = GA(g_xn_h, bf16), *xnl = GA(g_xn_l, bf16);
    bf16 *wqh = GA(g_wq_h, bf16), *wql = GA(g_wq_l, bf16);
    bf16 *wkh = GA(g_wk_h, bf16), *wkl = GA(g_wk_l, bf16);
    bf16 *wvh = GA(g_wv_h, bf16), *wvl = GA(g_wv_l, bf16);
    bf16 *wrh = GA(g_wr_h, bf16), *wrl = GA(g_wr_l, bf16);
    bf16 *woh = GA(g_wo_h, bf16), *wol = GA(g_wo_l, bf16);
    bf16 *w1h = GA(g_w1_h, bf16), *w1l = GA(g_w1_l, bf16);
    bf16 *w2h = GA(g_w2_h, bf16), *w2l = GA(g_w2_l, bf16);
    float *qf = GA(g_qf, float);
    bf16 *qwh = GA(g_qw_h, bf16), *qwl = GA(g_qw_l, bf16);
    bf16 *qrh = GA(g_qr_h, bf16), *qrl = GA(g_qr_l, bf16);
    bf16 *kh  = GA(g_k_h, bf16),  *kl  = GA(g_k_l, bf16);
    float *vf = GA(g_vf, float);
    bf16 *vTh = GA(g_vT_h, bf16), *vTl = GA(g_vT_l, bf16);
    bf16 *ph  = GA(g_pos_h, bf16),*pl  = GA(g_pos_l, bf16);
    bf16 *rkh = GA(g_rk_h, bf16), *rkl = GA(g_rk_l, bf16);
    float *cont = GA(g_cont, float);
    float *rel  = GA(g_rel, float);
    bf16 *ath = GA(g_at_h, bf16), *atl = GA(g_at_l, bf16);
    bf16 *oh  = GA(g_o_h, bf16),  *ol  = GA(g_o_l, bf16);
    float *y  = GA(g_y, float);
    bf16 *ynh = GA(g_yn_h, bf16), *ynl = GA(g_yn_l, bf16);
    bf16 *h1h = GA(g_h1_h, bf16), *h1l = GA(g_h1_l, bf16);
#undef GA

    cudaFuncSetAttribute(tgemm_kernel, cudaFuncAttributeMaxDynamicSharedMemorySize, SM_TOT);
    dim3 tb(32, 8);

    // LN1 + weight convert/transpose
    ln_kernel<<<TT, 256>>>(x, ln1_g, ln1_b, xnh, xnl);
    cvtT_kernel<<<dim3(QKC/32, CC/32), tb>>>(Wq, wqh, wql, CC, QKC);
    cvtT_kernel<<<dim3(QKC/32, CC/32), tb>>>(Wk, wkh, wkl, CC, QKC);
    cvtT_kernel<<<dim3(CC/32, CC/32), tb>>>(Wv, wvh, wvl, CC, CC);
    cvtT_kernel<<<dim3(QKC/32, FF/32), tb>>>(Wr, wrh, wrl, FF, QKC);
    cvtT_kernel<<<dim3(CC/32, CC/32), tb>>>(Wo, woh, wol, CC, CC);
    cvtT_kernel<<<dim3(2*CC/32, CC/32), tb>>>(W1, w1h, w1l, CC, 2*CC);
    cvtT_kernel<<<dim3(CC/32, 2*CC/32), tb>>>(W2, w2h, w2l, 2*CC, CC);

    // q fp32 (scaled), then +bias splits
    tgemm_kernel<<<dim3(QKC/128, TT/128, 1), 256, SM_TOT>>>(
        TT, QKC, CC, xnh, xnl, CC, 0, wqh, wql, CC, 0,
        qf, nullptr, nullptr, QKC, 0, nullptr, nullptr, 0, 0, 0.125f, 0, 0);
    cvtb_kernel<<<(TT*QKC+255)/256, 256>>>(qf, rwb, qwh, qwl, TT*QKC, QKC);
    cvtb_kernel<<<(TT*QKC+255)/256, 256>>>(qf, rrb, qrh, qrl, TT*QKC, QKC);

    // k, v
    tgemm_kernel<<<dim3(QKC/128, TT/128, 1), 256, SM_TOT>>>(
        TT, QKC, CC, xnh, xnl, CC, 0, wkh, wkl, CC, 0,
        nullptr, kh, kl, QKC, 0, nullptr, nullptr, 0, 0, 1.0f, 0, 0);
    tgemm_kernel<<<dim3(CC/128, TT/128, 1), 256, SM_TOT>>>(
        TT, CC, CC, xnh, xnl, CC, 0, wvh, wvl, CC, 0,
        vf, nullptr, nullptr, CC, 0, nullptr, nullptr, 0, 0, 1.0f, 0, 0);
    cvtT_kernel<<<dim3(CC/32, TT/32), tb>>>(vf, vTh, vTl, TT, CC);

    // positional + r_k
    pos_kernel<<<LLP, 32>>>(ph, pl);
    tgemm_kernel<<<dim3(QKC/128, LLP/128, 1), 256, SM_TOT>>>(
        LLP, QKC, FF, ph, pl, FF, 0, wrh, wrl, FF, 0,
        nullptr, rkh, rkl, QKC, 0, nullptr, nullptr, 0, 0, 1.0f, 0, 0);

    // content & rel logits
    tgemm_kernel<<<dim3(TT/128, TT/128, HH), 256, SM_TOT>>>(
        TT, TT, HK, qwh, qwl, QKC, HK, kh, kl, QKC, HK,
        cont, nullptr, nullptr, TT, (long long)TT*TT, nullptr, nullptr, 0, 0, 1.0f, 0, 0);
    tgemm_kernel<<<dim3(13, TT/128, HH), 256, SM_TOT>>>(
        TT, LLP, HK, qrh, qrl, QKC, HK, rkh, rkl, QKC, HK,
        rel, nullptr, nullptr, LLP, (long long)TT*LLP, nullptr, nullptr, 0, 0, 1.0f, 0, 1);

    // shift + softmax
    softmax_merge_kernel<<<HH*TT, 256>>>(cont, rel, ath, atl);

    // attn @ V
    tgemm_kernel<<<dim3(2, TT/128, HH), 256, SM_TOT>>>(
        TT, HV, TT, ath, atl, TT, (long long)TT*TT, vTh, vTl, TT, (long long)HV*TT,
        nullptr, oh, ol, CC, HV, nullptr, nullptr, 0, 0, 1.0f, 0, 0);

    // output projection + bias + residual
    tgemm_kernel<<<dim3(CC/128, TT/128, 1), 256, SM_TOT>>>(
        TT, CC, CC, oh, ol, CC, 0, woh, wol, CC, 0,
        y, nullptr, nullptr, CC, 0, bo, x, CC, 0, 1.0f, 0, 0);

    // LN2 + MLP
    ln_kernel<<<TT, 256>>>(y, ln2_g, ln2_b, ynh, ynl);
    tgemm_kernel<<<dim3(2*CC/128, TT/128, 1), 256, SM_TOT>>>(
        TT, 2*CC, CC, ynh, ynl, CC, 0, w1h, w1l, CC, 0,
        nullptr, h1h, h1l, 2*CC, 0, b1, nullptr, 0, 0, 1.0f, 1, 0);
    tgemm_kernel<<<dim3(CC/128, TT/128, 1), 256, SM_TOT>>>(
        TT, CC, 2*CC, h1h, h1l, 2*CC, 0, w2h, w2l, 2*CC, 0,
        out, nullptr, nullptr, CC, 0, b2, y, CC, 0, 1.0f, 0, 0);
}

// round 6
// speedup vs baseline: 2.8580x; 1.0296x over previous
#include <cuda_runtime.h>
#include <cuda_bf16.h>
#include <math.h>
#include <stdint.h>

#define TT 1536
#define CC 1536
#define HH 8
#define HK 64
#define HV 192
#define FF 192
#define QKC 512
#define LLP 3072
typedef __nv_bfloat16 bf16;

// ---------------- scratch ----------------
__device__ bf16 g_xn_h[TT*CC],  g_xn_l[TT*CC];
__device__ bf16 g_wq_h[QKC*CC], g_wq_l[QKC*CC];
__device__ bf16 g_wk_h[QKC*CC], g_wk_l[QKC*CC];
__device__ bf16 g_wv_h[CC*CC],  g_wv_l[CC*CC];
__device__ bf16 g_wr_h[QKC*FF], g_wr_l[QKC*FF];
__device__ bf16 g_wo_h[CC*CC],  g_wo_l[CC*CC];
__device__ bf16 g_w1_h[2*CC*CC],g_w1_l[2*CC*CC];
__device__ bf16 g_w2_h[CC*2*CC],g_w2_l[CC*2*CC];
__device__ bf16 g_qw_h[TT*QKC], g_qw_l[TT*QKC];
__device__ bf16 g_qr_h[TT*QKC], g_qr_l[TT*QKC];
__device__ bf16 g_k_h[TT*QKC],  g_k_l[TT*QKC];
__device__ float g_vf[TT*CC];
__device__ bf16 g_vT_h[CC*TT],  g_vT_l[CC*TT];
__device__ bf16 g_pos_h[LLP*FF],g_pos_l[LLP*FF];
__device__ bf16 g_rk_h[LLP*QKC],g_rk_l[LLP*QKC];
__device__ float g_cont[HH*TT*TT];
__device__ float g_rel[(size_t)HH*TT*LLP];
__device__ bf16 g_at_h[HH*TT*TT], g_at_l[HH*TT*TT];
__device__ bf16 g_o_h[TT*CC],   g_o_l[TT*CC];
__device__ float g_y[TT*CC];
__device__ bf16 g_yn_h[TT*CC],  g_yn_l[TT*CC];
__device__ bf16 g_h1_h[TT*2*CC],g_h1_l[TT*2*CC];

// ---------------- helpers ----------------
__device__ __forceinline__ uint32_t smem_u32(const void* p) {
    uint32_t a;
    asm("{ .reg .u64 t; cvta.to.shared.u64 t, %1; cvt.u32.u64 %0, t; }" : "=r"(a) : "l"(p));
    return a;
}
__device__ __forceinline__ void mma_bf16(float* c, const uint32_t* a, const uint32_t* b) {
    asm volatile("mma.sync.aligned.m16n8k16.row.col.f32.bf16.bf16.f32 "
        "{%0,%1,%2,%3},{%4,%5,%6,%7},{%8,%9},{%0,%1,%2,%3};"
        : "+f"(c[0]), "+f"(c[1]), "+f"(c[2]), "+f"(c[3])
        : "r"(a[0]), "r"(a[1]), "r"(a[2]), "r"(a[3]), "r"(b[0]), "r"(b[1]));
}
__device__ __forceinline__ void ldsm4(uint32_t* r, uint32_t addr) {
    asm volatile("ldmatrix.sync.aligned.m8n8.x4.shared.b16 {%0,%1,%2,%3}, [%4];"
        : "=r"(r[0]), "=r"(r[1]), "=r"(r[2]), "=r"(r[3]) : "r"(addr));
}
__device__ __forceinline__ void cpasync16(uint32_t dst, const void* src, uint32_t sz) {
    asm volatile("cp.async.ca.shared.global [%0], [%1], 16, %2;"
                 :: "r"(dst), "l"(src), "r"(sz) : "memory");
}
__device__ __forceinline__ void cp_commit() { asm volatile("cp.async.commit_group;" ::: "memory"); }
__device__ __forceinline__ void cp_wait2()  { asm volatile("cp.async.wait_group 2;" ::: "memory"); }
__device__ __forceinline__ uint32_t pack_bf2(float a, float b) {
    __nv_bfloat162 t = __floats2bfloat162_rn(a, b);
    return *reinterpret_cast<uint32_t*>(&t);
}
__device__ __forceinline__ float bfr(float x) { return __bfloat162float(__float2bfloat16(x)); }
__device__ __forceinline__ void split_bf(float v, bf16& h, bf16& l) {
    h = __float2bfloat16(v);
    l = __float2bfloat16(v - __bfloat162float(h));
}

// smem: 4 stages, K-chunk 16, 48B padded rows
#define ROWB 48
#define STG_AH 0
#define STG_AL 6144
#define STG_BH 12288
#define STG_BL 18432
#define STG_SZ 24576
#define SM_TOT (4*STG_SZ)

// ---------------- bf16x3 mma.sync GEMM, 4-stage cp.async pipeline ----------------
// C = alpha*A@B^T (+bias)(relu)(+res);  A[M,K], B[N,K] row-major, hi/lo pairs.
// Output: Cf fp32 OR (Ch,Cl) split [, + (Ch2,Cl2) with bias2].
// win: bn = (11 - by + bx)*128 (rel diagonal window).
__global__ __launch_bounds__(256, 2)
void tgemm_kernel(int M, int N, int K,
                  const bf16* __restrict__ Ah, const bf16* __restrict__ Al, int lda, long long sA,
                  const bf16* __restrict__ Bh, const bf16* __restrict__ Bl, int ldb, long long sB,
                  float* __restrict__ Cf, bf16* __restrict__ Ch, bf16* __restrict__ Cl,
                  bf16* __restrict__ Ch2, bf16* __restrict__ Cl2,
                  int ldc, long long sC,
                  const float* __restrict__ bias, const float* __restrict__ bias2,
                  const float* __restrict__ Rp, int ldr, long long sR,
                  float alpha, int relu, int win)
{
    extern __shared__ char smem[];
    uint32_t sbase = smem_u32(smem);
    int tid = threadIdx.x, wid = tid >> 5, lane = tid & 31;
    int grp = lane >> 2, tig = lane & 3;
    int wm = wid & 1, wn = wid >> 1;
    int z = blockIdx.z;
    Ah += (long long)z * sA;  Al += (long long)z * sA;
    Bh += (long long)z * sB;  Bl += (long long)z * sB;
    const float* Rb = Rp ? Rp + (long long)z * sR : nullptr;
    int bm = blockIdx.y * 128;
    int bn = win ? (11 - blockIdx.y + blockIdx.x) * 128 : blockIdx.x * 128;

    const int nch = K >> 4;
    // staging: 2 threads/row, 1 x 16B seg each per matrix
    const int sr = tid >> 1;
    const int ss = tid & 1;
    const bool bval = (bn + sr) < N;
    const uint32_t bvsz = bval ? 16u : 0u;
    const uint32_t sdst = sr * ROWB + ss * 16;

    const bf16* gAh = Ah + (size_t)(bm + sr) * lda + ss * 8;
    const bf16* gAl = Al + (size_t)(bm + sr) * lda + ss * 8;
    const bf16* gBh = Bh + (size_t)(bn + sr) * ldb + ss * 8;
    const bf16* gBl = Bl + (size_t)(bn + sr) * ldb + ss * 8;

    // ldmatrix lane offsets
    const uint32_t lA = (uint32_t)(lane & 15) * ROWB + (uint32_t)(lane >> 4) * 16;
    const uint32_t lB = ((uint32_t)((lane >> 4) * 8 + (lane & 7))) * ROWB + (uint32_t)((lane >> 3) & 1) * 16;

    float acc[4][4][4];
#pragma unroll
    for (int a = 0; a < 4; a++)
#pragma unroll
        for (int b = 0; b < 4; b++)
#pragma unroll
            for (int r = 0; r < 4; r++) acc[a][b][r] = 0.f;

    // prologue: stages 0..2
#pragma unroll
    for (int s = 0; s < 3; s++) {
        if (s < nch) {
            uint32_t st = sbase + s * STG_SZ + sdst;
            int k0 = s << 4;
            cpasync16(st + STG_AH, gAh + k0, 16);
            cpasync16(st + STG_AL, gAl + k0, 16);
            cpasync16(st + STG_BH, gBh + k0, bvsz);
            cpasync16(st + STG_BL, gBl + k0, bvsz);
        }
        cp_commit();
    }

    for (int c = 0; c < nch; c++) {
        cp_wait2();
        __syncthreads();
        uint32_t stg = sbase + (c & 3) * STG_SZ;

        uint32_t bh[2][4], bl[2][4];
#pragma unroll
        for (int p = 0; p < 2; p++) {
            uint32_t ba = stg + (uint32_t)(wn * 32 + p * 16) * ROWB + lB;
            ldsm4(bh[p], ba + STG_BH);
            ldsm4(bl[p], ba + STG_BL);
        }
#pragma unroll
        for (int ms = 0; ms < 4; ms++) {
            uint32_t aa = stg + (uint32_t)(wm * 64 + ms * 16) * ROWB + lA;
            uint32_t ah[4], al[4];
            ldsm4(ah, aa + STG_AH);
            ldsm4(al, aa + STG_AL);
#pragma unroll
            for (int ns = 0; ns < 4; ns++) {
                uint32_t* bhp = &bh[ns >> 1][(ns & 1) * 2];
                uint32_t* blp = &bl[ns >> 1][(ns & 1) * 2];
                mma_bf16(acc[ms][ns], ah, bhp);
                mma_bf16(acc[ms][ns], ah, blp);
                mma_bf16(acc[ms][ns], al, bhp);
            }
        }

        if (c + 3 < nch) {
            uint32_t st = sbase + ((c + 3) & 3) * STG_SZ + sdst;
            int k0 = (c + 3) << 4;
            cpasync16(st + STG_AH, gAh + k0, 16);
            cpasync16(st + STG_AL, gAl + k0, 16);
            cpasync16(st + STG_BH, gBh + k0, bvsz);
            cpasync16(st + STG_BL, gBl + k0, bvsz);
        }
        cp_commit();
    }

    // epilogue
    Cf  = Cf  ? Cf  + (long long)z * sC : nullptr;
    Ch  = Ch  ? Ch  + (long long)z * sC : nullptr;
    Cl  = Cl  ? Cl  + (long long)z * sC : nullptr;
    const bool has_bias = (bias != nullptr);
#pragma unroll
    for (int ms = 0; ms < 4; ms++) {
        int row0 = bm + wm * 64 + ms * 16 + grp;
#pragma unroll
        for (int ns = 0; ns < 4; ns++) {
            int col = bn + wn * 32 + ns * 8 + (tig << 1);
            if (col >= N) continue;
#pragma unroll
            for (int h = 0; h < 2; h++) {
                int m = row0 + h * 8;
                float a0 = alpha * acc[ms][ns][h * 2 + 0];
                float a1 = alpha * acc[ms][ns][h * 2 + 1];
                float v0 = a0, v1 = a1;
                if (has_bias) { v0 += bias[col]; v1 += bias[col + 1]; }
                if (relu) { v0 = fmaxf(v0, 0.f); v1 = fmaxf(v1, 0.f); }
                if (Cf) {
                    if (Rb) {
                        const float* rp = Rb + (size_t)m * ldr + col;
                        v0 += rp[0]; v1 += rp[1];
                    }
                    *(float2*)(Cf + (size_t)m * ldc + col) = make_float2(v0, v1);
                } else {
                    *(uint32_t*)(Ch + (size_t)m * ldc + col) = pack_bf2(v0, v1);
                    *(uint32_t*)(Cl + (size_t)m * ldc + col) =
                        pack_bf2(v0 - bfr(v0), v1 - bfr(v1));
                    if (Ch2) {
                        float u0 = a0 + bias2[col], u1 = a1 + bias2[col + 1];
                        *(uint32_t*)(Ch2 + (size_t)m * ldc + col) = pack_bf2(u0, u1);
                        *(uint32_t*)(Cl2 + (size_t)m * ldc + col) =
                            pack_bf2(u0 - bfr(u0), u1 - bfr(u1));
                    }
                }
            }
        }
    }
}

// ---------------- LayerNorm -> bf16 hi/lo ----------------
__global__ void ln_kernel(const float* __restrict__ x, const float* __restrict__ g,
                          const float* __restrict__ b, bf16* __restrict__ oh, bf16* __restrict__ ol) {
    int row = blockIdx.x;
    const float* xr = x + (size_t)row * CC;
    float s = 0.f, sq = 0.f;
    for (int c = threadIdx.x; c < CC; c += blockDim.x) { float v = xr[c]; s += v; sq += v * v; }
    __shared__ float rs[256], rq[256];
    rs[threadIdx.x] = s; rq[threadIdx.x] = sq; __syncthreads();
    for (int st = 128; st > 0; st >>= 1) {
        if (threadIdx.x < st) { rs[threadIdx.x] += rs[threadIdx.x + st]; rq[threadIdx.x] += rq[threadIdx.x + st]; }
        __syncthreads();
    }
    float mean = rs[0] / CC;
    float var  = rq[0] / CC - mean * mean;
    float rstd = rsqrtf(var + 1e-3f);
    for (int c = threadIdx.x; c < CC; c += blockDim.x) {
        float v = (xr[c] - mean) * rstd * g[c] + b[c];
        bf16 h, l; split_bf(v, h, l);
        oh[(size_t)row * CC + c] = h;
        ol[(size_t)row * CC + c] = l;
    }
}

// ---------------- transpose+convert ----------------
__global__ void cvtT_kernel(const float* __restrict__ in, bf16* __restrict__ oh,
                            bf16* __restrict__ ol, int R, int Cc) {
    __shared__ float t[32][33];
    int bx = blockIdx.x * 32, by = blockIdx.y * 32;
    int x = bx + threadIdx.x;
    for (int i = threadIdx.y; i < 32; i += 8)
        t[i][threadIdx.x] = in[(size_t)(by + i) * Cc + x];
    __syncthreads();
    int xo = by + threadIdx.x;
    for (int i = threadIdx.y; i < 32; i += 8) {
        float v = t[threadIdx.x][i];
        bf16 h, l; split_bf(v, h, l);
        oh[(size_t)(bx + i) * R + xo] = h;
        ol[(size_t)(bx + i) * R + xo] = l;
    }
}

// ---------------- positional features ----------------
__global__ void pos_kernel(bf16* __restrict__ oh, bf16* __restrict__ ol) {
    int row = blockIdx.x;
    int i   = threadIdx.x;
    float p  = (float)(row - (TT - 1));
    float ap = fabsf(p);
    float sg = (p > 0.f) ? 1.f : ((p < 0.f) ? -1.f : 0.f);

    double log2T = log(1536.0) / log(2.0);
    double hl    = exp2(3.0 + (double)i * (log2T - 3.0) / 31.0);
    float coef   = (float)(-0.6931471805599453 / hl);
    float fe     = expf(coef * ap);

    float width = (float)(exp2((double)(i + 1)) - 1.0);
    float fcm   = (width > ap) ? 1.f : 0.f;

    double mean = 48.0 * (double)(i + 1);
    double stdv = 24.0;
    float conc  = (float)((mean / stdv) * (mean / stdv));
    float rate  = (float)(mean / (stdv * stdv));
    double lu   = (double)(conc - 1.f) * log((double)ap) - (double)rate * (double)ap;
    double lnn  = lgamma((double)conc) - (double)conc * log((double)rate);
    float prob  = (float)exp(lu - lnn) + 1e-8f;

    float mx = prob;
#pragma unroll
    for (int o = 16; o > 0; o >>= 1) mx = fmaxf(mx, __shfl_xor_sync(0xffffffffu, mx, o));
    float fg = prob / mx;

    float vals[6] = { fe, fcm, fg, sg * fe, sg * fcm, sg * fg };
    size_t base = (size_t)row * FF;
#pragma unroll
    for (int c = 0; c < 6; c++) {
        bf16 h, l; split_bf(vals[c], h, l);
        oh[base + c * 32 + i] = h;
        ol[base + c * 32 + i] = l;
    }
}

// ---------------- fused shift + softmax -> attn bf16 hi/lo (512 thr, float4) ----------------
__global__ void softmax_merge_kernel(const float* __restrict__ cont, const float* __restrict__ rel,
                                     bf16* __restrict__ ah, bf16* __restrict__ al) {
    int row = blockIdx.x;
    int q = row % TT;
    const float* cr = cont + (size_t)row * TT;
    const float* rr = rel + (size_t)row * LLP + (TT - 1 - q);
    __shared__ float red[512];
    __shared__ float ebuf[TT];
    int t = threadIdx.x;
    // rr is 4-aligned iff (TT-1-q) % 4 == 0; handle generic alignment with scalar rel loads
    float m = -1e30f;
    for (int j4 = t; j4 < TT / 4; j4 += 512) {
        float4 c4 = *(const float4*)(cr + j4 * 4);
        float s0 = c4.x + rr[j4 * 4 + 0];
        float s1 = c4.y + rr[j4 * 4 + 1];
        float s2 = c4.z + rr[j4 * 4 + 2];
        float s3 = c4.w + rr[j4 * 4 + 3];
        ebuf[j4 * 4 + 0] = s0; ebuf[j4 * 4 + 1] = s1;
        ebuf[j4 * 4 + 2] = s2; ebuf[j4 * 4 + 3] = s3;
        m = fmaxf(m, fmaxf(fmaxf(s0, s1), fmaxf(s2, s3)));
    }
    red[t] = m; __syncthreads();
    for (int st = 256; st > 0; st >>= 1) {
        if (t < st) red[t] = fmaxf(red[t], red[t + st]);
        __syncthreads();
    }
    m = red[0]; __syncthreads();
    float s = 0.f;
    for (int j = t; j < TT; j += 512) {
        float e = expf(ebuf[j] - m);
        ebuf[j] = e; s += e;
    }
    red[t] = s; __syncthreads();
    for (int st = 256; st > 0; st >>= 1) {
        if (t < st) red[t] += red[t + st];
        __syncthreads();
    }
    float inv = 1.f / red[0];
    for (int j2 = t; j2 < TT / 2; j2 += 512) {
        float v0 = ebuf[j2 * 2] * inv, v1 = ebuf[j2 * 2 + 1] * inv;
        *(uint32_t*)(ah + (size_t)row * TT + j2 * 2) = pack_bf2(v0, v1);
        *(uint32_t*)(al + (size_t)row * TT + j2 * 2) =
            pack_bf2(v0 - bfr(v0), v1 - bfr(v1));
    }
}

// ---------------- host launch ----------------
extern "C" void kernel_launch(void* const* d_in, const int* in_sizes, int n_in,
                              void* d_out, int out_size) {
    const float* x     = (const float*)d_in[0];
    const float* ln1_g = (const float*)d_in[1];
    const float* ln1_b = (const float*)d_in[2];
    const float* ln2_g = (const float*)d_in[3];
    const float* ln2_b = (const float*)d_in[4];
    const float* Wq    = (const float*)d_in[5];
    const float* Wk    = (const float*)d_in[6];
    const float* Wv    = (const float*)d_in[7];
    const float* Wr    = (const float*)d_in[8];
    const float* Wo    = (const float*)d_in[9];
    const float* bo    = (const float*)d_in[10];
    const float* rwb   = (const float*)d_in[11];
    const float* rrb   = (const float*)d_in[12];
    const float* W1    = (const float*)d_in[13];
    const float* b1    = (const float*)d_in[14];
    const float* W2    = (const float*)d_in[15];
    const float* b2    = (const float*)d_in[16];
    float* out = (float*)d_out;

#define GA(sym, ty) ({ void* p_; cudaGetSymbolAddress(&p_, sym); (ty*)p_; })
    bf16 *xnh = GA(g_xn_h, bf16), *xnl = GA(g_xn_l, bf16);
    bf16 *wqh = GA(g_wq_h, bf16), *wql = GA(g_wq_l, bf16);
    bf16 *wkh = GA(g_wk_h, bf16), *wkl = GA(g_wk_l, bf16);
    bf16 *wvh = GA(g_wv_h, bf16), *wvl = GA(g_wv_l, bf16);
    bf16 *wrh = GA(g_wr_h, bf16), *wrl = GA(g_wr_l, bf16);
    bf16 *woh = GA(g_wo_h, bf16), *wol = GA(g_wo_l, bf16);
    bf16 *w1h = GA(g_w1_h, bf16), *w1l = GA(g_w1_l, bf16);
    bf16 *w2h = GA(g_w2_h, bf16), *w2l = GA(g_w2_l, bf16);
    bf16 *qwh = GA(g_qw_h, bf16), *qwl = GA(g_qw_l, bf16);
    bf16 *qrh = GA(g_qr_h, bf16), *qrl = GA(g_qr_l, bf16);
    bf16 *kh  = GA(g_k_h, bf16),  *kl  = GA(g_k_l, bf16);
    float *vf = GA(g_vf, float);
    bf16 *vTh = GA(g_vT_h, bf16), *vTl = GA(g_vT_l, bf16);
    bf16 *ph  = GA(g_pos_h, bf16),*pl  = GA(g_pos_l, bf16);
    bf16 *rkh = GA(g_rk_h, bf16), *rkl = GA(g_rk_l, bf16);
    float *cont = GA(g_cont, float);
    float *rel  = GA(g_rel, float);
    bf16 *ath = GA(g_at_h, bf16), *atl = GA(g_at_l, bf16);
    bf16 *oh  = GA(g_o_h, bf16),  *ol  = GA(g_o_l, bf16);
    float *y  = GA(g_y, float);
    bf16 *ynh = GA(g_yn_h, bf16), *ynl = GA(g_yn_l, bf16);
    bf16 *h1h = GA(g_h1_h, bf16), *h1l = GA(g_h1_l, bf16);
#undef GA

    cudaFuncSetAttribute(tgemm_kernel, cudaFuncAttributeMaxDynamicSharedMemorySize, SM_TOT);
    dim3 tb(32, 8);

    // launches 0-4 (ordered so launch #5 = V-projection tgemm for ncu)
    cvtT_kernel<<<dim3(CC/32, CC/32), tb>>>(Wv, wvh, wvl, CC, CC);          // 0
    ln_kernel<<<TT, 256>>>(x, ln1_g, ln1_b, xnh, xnl);                       // 1
    pos_kernel<<<LLP, 32>>>(ph, pl);                                         // 2
    cvtT_kernel<<<dim3(QKC/32, CC/32), tb>>>(Wq, wqh, wql, CC, QKC);         // 3
    cvtT_kernel<<<dim3(QKC/32, CC/32), tb>>>(Wk, wkh, wkl, CC, QKC);         // 4

    // 5: V projection (profiled)
    tgemm_kernel<<<dim3(CC/128, TT/128, 1), 256, SM_TOT>>>(
        TT, CC, CC, xnh, xnl, CC, 0, wvh, wvl, CC, 0,
        vf, nullptr, nullptr, nullptr, nullptr, CC, 0,
        nullptr, nullptr, nullptr, 0, 0, 1.0f, 0, 0);

    cvtT_kernel<<<dim3(QKC/32, FF/32), tb>>>(Wr, wrh, wrl, FF, QKC);
    cvtT_kernel<<<dim3(CC/32, CC/32), tb>>>(Wo, woh, wol, CC, CC);
    cvtT_kernel<<<dim3(2*CC/32, CC/32), tb>>>(W1, w1h, w1l, CC, 2*CC);
    cvtT_kernel<<<dim3(CC/32, 2*CC/32), tb>>>(W2, w2h, w2l, 2*CC, CC);
    cvtT_kernel<<<dim3(CC/32, TT/32), tb>>>(vf, vTh, vTl, TT, CC);

    // q: fused dual bias split (qw = 0.125*q + rwb, qr = 0.125*q + rrb)
    tgemm_kernel<<<dim3(QKC/128, TT/128, 1), 256, SM_TOT>>>(
        TT, QKC, CC, xnh, xnl, CC, 0, wqh, wql, CC, 0,
        nullptr, qwh, qwl, qrh, qrl, QKC, 0,
        rwb, rrb, nullptr, 0, 0, 0.125f, 0, 0);

    // k
    tgemm_kernel<<<dim3(QKC/128, TT/128, 1), 256, SM_TOT>>>(
        TT, QKC, CC, xnh, xnl, CC, 0, wkh, wkl, CC, 0,
        nullptr, kh, kl, nullptr, nullptr, QKC, 0,
        nullptr, nullptr, nullptr, 0, 0, 1.0f, 0, 0);

    // r_k projection
    tgemm_kernel<<<dim3(QKC/128, LLP/128, 1), 256, SM_TOT>>>(
        LLP, QKC, FF, ph, pl, FF, 0, wrh, wrl, FF, 0,
        nullptr, rkh, rkl, nullptr, nullptr, QKC, 0,
        nullptr, nullptr, nullptr, 0, 0, 1.0f, 0, 0);

    // content & rel logits
    tgemm_kernel<<<dim3(TT/128, TT/128, HH), 256, SM_TOT>>>(
        TT, TT, HK, qwh, qwl, QKC, HK, kh, kl, QKC, HK,
        cont, nullptr, nullptr, nullptr, nullptr, TT, (long long)TT*TT,
        nullptr, nullptr, nullptr, 0, 0, 1.0f, 0, 0);
    tgemm_kernel<<<dim3(13, TT/128, HH), 256, SM_TOT>>>(
        TT, LLP, HK, qrh, qrl, QKC, HK, rkh, rkl, QKC, HK,
        rel, nullptr, nullptr, nullptr, nullptr, LLP, (long long)TT*LLP,
        nullptr, nullptr, nullptr, 0, 0, 1.0f, 0, 1);

    // shift + softmax
    softmax_merge_kernel<<<HH*TT, 512>>>(cont, rel, ath, atl);

    // attn @ V
    tgemm_kernel<<<dim3(2, TT/128, HH), 256, SM_TOT>>>(
        TT, HV, TT, ath, atl, TT, (long long)TT*TT, vTh, vTl, TT, (long long)HV*TT,
        nullptr, oh, ol, nullptr, nullptr, CC, HV,
        nullptr, nullptr, nullptr, 0, 0, 1.0f, 0, 0);

    // output projection + bias + residual
    tgemm_kernel<<<dim3(CC/128, TT/128, 1), 256, SM_TOT>>>(
        TT, CC, CC, oh, ol, CC, 0, woh, wol, CC, 0,
        y, nullptr, nullptr, nullptr, nullptr, CC, 0,
        bo, nullptr, x, CC, 0, 1.0f, 0, 0);

    // LN2 + MLP
    ln_kernel<<<TT, 256>>>(y, ln2_g, ln2_b, ynh, ynl);
    tgemm_kernel<<<dim3(2*CC/128, TT/128, 1), 256, SM_TOT>>>(
        TT, 2*CC, CC, ynh, ynl, CC, 0, w1h, w1l, CC, 0,
        nullptr, h1h, h1l, nullptr, nullptr, 2*CC, 0,
        b1, nullptr, nullptr, 0, 0, 1.0f, 1, 0);
    tgemm_kernel<<<dim3(CC/128, TT/128, 1), 256, SM_TOT>>>(
        TT, CC, 2*CC, h1h, h1l, 2*CC, 0, w2h, w2l, 2*CC, 0,
        out, nullptr, nullptr, nullptr, nullptr, CC, 0,
        b2, nullptr, y, CC, 0, 1.0f, 0, 0);
}